// round 1
// baseline (speedup 1.0000x reference)
#include <cuda_runtime.h>
#include <math_constants.h>
#include <float.h>

// Problem constants (fixed by setup_inputs): B=64, Nt=64, Ns=4096, C=256,
// WIN=2, TOPK=3, GH=GW=4, 16 gabor kernels.
#define BMAX 64

__device__ float g_zmax[BMAX * 256];
__device__ float g_winsum[BMAX * 1024];
__device__ int   g_topk[BMAX * 3];

// ---------------------------------------------------------------------------
// Kernel 1: z_max[b,c] = max over 64 tokens of z[b,t,c]
// ---------------------------------------------------------------------------
__global__ void k_zmax(const float* __restrict__ z) {
    int b = blockIdx.x, c = threadIdx.x;
    const float* p = z + ((size_t)b * 64) * 256 + c;
    float m = -FLT_MAX;
#pragma unroll 8
    for (int t = 0; t < 64; ++t) m = fmaxf(m, p[t * 256]);
    g_zmax[b * 256 + c] = m;
}

// ---------------------------------------------------------------------------
// Kernel 2: per-window sum of response over the 4 pixels of each 2x2 window.
// winsum[b, wh*32+ww] = sum_{i,j} dot(x[b, (2wh+i)*64 + 2ww+j, :], zmax[b,:])
// One block per (b, wh). 8 warps, each warp handles 4 windows.
// ---------------------------------------------------------------------------
__global__ void k_winsum(const float* __restrict__ x) {
    int b  = blockIdx.x >> 5;
    int wh = blockIdx.x & 31;
    __shared__ float4 sz[64];
    int tid = threadIdx.x;
    if (tid < 64) sz[tid] = ((const float4*)(g_zmax + b * 256))[tid];
    __syncthreads();

    int warp = tid >> 5, lane = tid & 31;
    const float* xb = x + (size_t)b * 4096 * 256 + (size_t)wh * 128 * 256;

#pragma unroll
    for (int q = 0; q < 4; ++q) {
        int ww = warp * 4 + q;
        const float* p = xb + ww * 2 * 256;
        float acc = 0.f;
#pragma unroll
        for (int r = 0; r < 4; ++r) {
            int off = ((r >> 1) * 64 + (r & 1)) * 256;  // rows s, s+1, s+64, s+65
            const float4* p4 = (const float4*)(p + off);
            float4 a  = p4[lane];       float4 za = sz[lane];
            acc += a.x * za.x + a.y * za.y + a.z * za.z + a.w * za.w;
            float4 bb = p4[lane + 32];  float4 zb = sz[lane + 32];
            acc += bb.x * zb.x + bb.y * zb.y + bb.z * zb.z + bb.w * zb.w;
        }
#pragma unroll
        for (int o = 16; o > 0; o >>= 1) acc += __shfl_down_sync(0xffffffffu, acc, o);
        if (lane == 0) g_winsum[b * 1024 + wh * 32 + ww] = acc;
    }
}

// ---------------------------------------------------------------------------
// Kernel 3: top-3 argmax over the 1024 window sums per batch.
// Descending values; ties broken by lowest index (matches jax.lax.top_k).
// ---------------------------------------------------------------------------
__global__ void k_topk() {
    int b = blockIdx.x;
    __shared__ float sv[1024];
    __shared__ float rv[256];
    __shared__ int   ri[256];
    int tid = threadIdx.x;
#pragma unroll
    for (int k = 0; k < 4; ++k) sv[tid + k * 256] = g_winsum[b * 1024 + tid + k * 256];
    __syncthreads();

    for (int r = 0; r < 3; ++r) {
        float bv = -FLT_MAX; int bi = 1 << 30;
#pragma unroll
        for (int k = 0; k < 4; ++k) {
            int i = tid + k * 256;
            float v = sv[i];
            if (v > bv || (v == bv && i < bi)) { bv = v; bi = i; }
        }
        rv[tid] = bv; ri[tid] = bi;
        __syncthreads();
        for (int s = 128; s > 0; s >>= 1) {
            if (tid < s) {
                float ov = rv[tid + s]; int oi = ri[tid + s];
                if (ov > rv[tid] || (ov == rv[tid] && oi < ri[tid])) { rv[tid] = ov; ri[tid] = oi; }
            }
            __syncthreads();
        }
        if (tid == 0) { g_topk[b * 3 + r] = ri[0]; sv[ri[0]] = -FLT_MAX; }
        __syncthreads();
    }
}

// ---------------------------------------------------------------------------
// Kernel 4: gather selected windows, bilinear 2->4 upsample, scale by (1+gmap).
// Block per (b, t); one thread per channel. Threads 0..15 build the gabor map.
// jax half-pixel bilinear 2->4 weights: {1,0},{.75,.25},{.25,.75},{0,1}.
// ---------------------------------------------------------------------------
__global__ void k_out(const float* __restrict__ x,
                      const float* __restrict__ gth, const float* __restrict__ gsg,
                      const float* __restrict__ glm, const float* __restrict__ gps,
                      const float* __restrict__ ggm, const float* __restrict__ gwt,
                      float* __restrict__ out) {
    __shared__ float s_gmap[16];
    int bt = blockIdx.x;
    int b = bt / 3, t = bt % 3;
    int c = threadIdx.x;

    if (c < 16) {
        int h = c >> 2, w = c & 3;
        float yy = (float)h - 1.5f;
        float xx = (float)w - 1.5f;
        float acc = 0.f;
        for (int k = 0; k < 16; ++k) {
            float theta = gth[k] * (2.f * CUDART_PI_F);
            float ct = cosf(theta), st = sinf(theta);
            float xp =  xx * ct + yy * st;
            float yp = -xx * st + yy * ct;
            float sig = gsg[k] + 0.5f;
            float lmb = glm[k] + 0.5f;
            float gam = ggm[k];
            float env = expf(-(xp * xp + gam * gam * yp * yp) / (2.f * sig * sig));
            float car = cosf(2.f * CUDART_PI_F * xp / lmb + gps[k]);
            acc += gwt[k] * env * car;
        }
        s_gmap[c] = 1.f + acc;   // splat + x_up = x_up * (1 + gmap)
    }
    __syncthreads();

    int widx = g_topk[b * 3 + t];
    int wh = widx >> 5, ww = widx & 31;
    const float* p = x + ((size_t)b * 4096 + wh * 128 + ww * 2) * 256 + c;
    float v00 = p[0];          // (i=0,j=0)
    float v01 = p[256];        // (i=0,j=1)
    float v10 = p[64 * 256];   // (i=1,j=0)
    float v11 = p[65 * 256];   // (i=1,j=1)

    const float wa[4] = {1.f, 0.75f, 0.25f, 0.f};
    const float wb[4] = {0.f, 0.25f, 0.75f, 1.f};

    float* ob = out + ((size_t)b * 48 + t * 16) * 256 + c;
#pragma unroll
    for (int gh = 0; gh < 4; ++gh) {
        float u0 = wa[gh] * v00 + wb[gh] * v10;  // interp along i (rows)
        float u1 = wa[gh] * v01 + wb[gh] * v11;
#pragma unroll
        for (int gw = 0; gw < 4; ++gw) {
            float val = wa[gw] * u0 + wb[gw] * u1;  // interp along j (cols)
            ob[(gh * 4 + gw) * 256] = val * s_gmap[gh * 4 + gw];
        }
    }
}

// ---------------------------------------------------------------------------
extern "C" void kernel_launch(void* const* d_in, const int* in_sizes, int n_in,
                              void* d_out, int out_size) {
    const float* z = (const float*)d_in[0];
    const float* x = (const float*)d_in[1];
    const float* gth = (const float*)d_in[2];
    const float* gsg = (const float*)d_in[3];
    const float* glm = (const float*)d_in[4];
    const float* gps = (const float*)d_in[5];
    const float* ggm = (const float*)d_in[6];
    const float* gwt = (const float*)d_in[7];
    float* out = (float*)d_out;

    int B = in_sizes[0] / (64 * 256);   // z is (B, 64, 256)

    k_zmax  <<<B,      256>>>(z);
    k_winsum<<<B * 32, 256>>>(x);
    k_topk  <<<B,      256>>>();
    k_out   <<<B * 3,  256>>>(x, gth, gsg, glm, gps, ggm, gwt, out);
}

// round 2
// speedup vs baseline: 1.0264x; 1.0264x over previous
#include <cuda_runtime.h>
#include <math_constants.h>
#include <float.h>

// Problem constants (fixed by setup_inputs): B=64, Nt=64, Ns=4096, C=256,
// WIN=2, TOPK=3, GH=GW=4, 16 gabor kernels.
#define BMAX 64

__device__ float g_zmax[BMAX * 256];
__device__ float g_winsum[BMAX * 1024];
__device__ float g_gmap[16];

// ---------------------------------------------------------------------------
// Kernel 1: z_max[b,c] = max over 64 tokens of z[b,t,c].
// Block 0 additionally computes the 4x4 gabor map (1 + sum_k w_k * gabor_k)
// on threads 0..15 — runs in parallel with the other 63 blocks.
// ---------------------------------------------------------------------------
__global__ void k_zmax(const float* __restrict__ z,
                       const float* __restrict__ gth, const float* __restrict__ gsg,
                       const float* __restrict__ glm, const float* __restrict__ gps,
                       const float* __restrict__ ggm, const float* __restrict__ gwt) {
    int b = blockIdx.x, c = threadIdx.x;
    const float* p = z + ((size_t)b * 64) * 256 + c;
    float m = -FLT_MAX;
#pragma unroll 8
    for (int t = 0; t < 64; ++t) m = fmaxf(m, p[t * 256]);
    g_zmax[b * 256 + c] = m;

    if (b == 0 && c < 16) {
        int h = c >> 2, w = c & 3;
        float yy = (float)h - 1.5f;
        float xx = (float)w - 1.5f;
        float acc = 0.f;
        for (int k = 0; k < 16; ++k) {
            float theta = gth[k] * (2.f * CUDART_PI_F);
            float ct = cosf(theta), st = sinf(theta);
            float xp =  xx * ct + yy * st;
            float yp = -xx * st + yy * ct;
            float sig = gsg[k] + 0.5f;
            float lmb = glm[k] + 0.5f;
            float gam = ggm[k];
            float env = expf(-(xp * xp + gam * gam * yp * yp) / (2.f * sig * sig));
            float car = cosf(2.f * CUDART_PI_F * xp / lmb + gps[k]);
            acc += gwt[k] * env * car;
        }
        g_gmap[c] = 1.f + acc;   // splat + x_up = x_up * (1 + gmap)
    }
}

// ---------------------------------------------------------------------------
// Kernel 2: per-window sum of response over the 4 pixels of each 2x2 window.
// winsum[b, wh*32+ww] = sum_{i,j} dot(x[b, (2wh+i)*64 + 2ww+j, :], zmax[b,:])
// One block per (b, wh). 8 warps; each warp owns 4 windows with independent
// accumulators; loads front-batched per row-pair for MLP; shuffles at end.
// ---------------------------------------------------------------------------
__global__ void __launch_bounds__(256) k_winsum(const float* __restrict__ x) {
    int b  = blockIdx.x >> 5;
    int wh = blockIdx.x & 31;
    __shared__ float4 sz[64];
    int tid = threadIdx.x;
    if (tid < 64) sz[tid] = ((const float4*)(g_zmax + b * 256))[tid];
    __syncthreads();

    int warp = tid >> 5, lane = tid & 31;
    const float* xb = x + (size_t)b * 4096 * 256 + (size_t)wh * 128 * 256
                        + (size_t)warp * 4 * 2 * 256;

    float acc[4] = {0.f, 0.f, 0.f, 0.f};
#pragma unroll
    for (int r = 0; r < 4; ++r) {
        int off = ((r >> 1) * 64 + (r & 1)) * 256;   // rows s, s+1, s+64, s+65
        float4 va[4], vb[4];
#pragma unroll
        for (int q = 0; q < 4; ++q) {                // batch 8 loads before FMAs
            const float4* p4 = (const float4*)(xb + q * 512 + off);
            va[q] = p4[lane];
            vb[q] = p4[lane + 32];
        }
        float4 za = sz[lane], zb = sz[lane + 32];
#pragma unroll
        for (int q = 0; q < 4; ++q) {
            acc[q] += va[q].x * za.x + va[q].y * za.y + va[q].z * za.z + va[q].w * za.w;
            acc[q] += vb[q].x * zb.x + vb[q].y * zb.y + vb[q].z * zb.z + vb[q].w * zb.w;
        }
    }
#pragma unroll
    for (int q = 0; q < 4; ++q) {
        float a = acc[q];
#pragma unroll
        for (int o = 16; o > 0; o >>= 1) a += __shfl_down_sync(0xffffffffu, a, o);
        if (lane == 0) g_winsum[b * 1024 + wh * 32 + warp * 4 + q] = a;
    }
}

// ---------------------------------------------------------------------------
// Kernel 3 (fused tail): per-batch top-3 window select (descending, ties ->
// lowest index, matching jax.lax.top_k), then gather + bilinear 2->4 upsample
// + (1+gmap) scale + write. One block per batch, thread per channel.
// jax half-pixel bilinear 2->4 weights: {1,0},{.75,.25},{.25,.75},{0,1}.
// ---------------------------------------------------------------------------
__global__ void __launch_bounds__(256) k_tail(const float* __restrict__ x,
                                              float* __restrict__ out) {
    int b = blockIdx.x;
    __shared__ float sv[1024];
    __shared__ float rv[256];
    __shared__ int   ri[256];
    __shared__ int   sidx[3];
    __shared__ float s_gmap[16];
    int tid = threadIdx.x;
#pragma unroll
    for (int k = 0; k < 4; ++k) sv[tid + k * 256] = g_winsum[b * 1024 + tid + k * 256];
    if (tid < 16) s_gmap[tid] = g_gmap[tid];
    __syncthreads();

    for (int r = 0; r < 3; ++r) {
        float bv = -FLT_MAX; int bi = 1 << 30;
#pragma unroll
        for (int k = 0; k < 4; ++k) {
            int i = tid + k * 256;
            float v = sv[i];
            if (v > bv || (v == bv && i < bi)) { bv = v; bi = i; }
        }
        rv[tid] = bv; ri[tid] = bi;
        __syncthreads();
        for (int s = 128; s > 0; s >>= 1) {
            if (tid < s) {
                float ov = rv[tid + s]; int oi = ri[tid + s];
                if (ov > rv[tid] || (ov == rv[tid] && oi < ri[tid])) { rv[tid] = ov; ri[tid] = oi; }
            }
            __syncthreads();
        }
        if (tid == 0) { sidx[r] = ri[0]; sv[ri[0]] = -FLT_MAX; }
        __syncthreads();
    }

    const float wa[4] = {1.f, 0.75f, 0.25f, 0.f};
    const float wb[4] = {0.f, 0.25f, 0.75f, 1.f};
    int c = tid;

#pragma unroll
    for (int t = 0; t < 3; ++t) {
        int widx = sidx[t];
        int wh = widx >> 5, ww = widx & 31;
        const float* p = x + ((size_t)b * 4096 + wh * 128 + ww * 2) * 256 + c;
        float v00 = p[0];          // (i=0,j=0)
        float v01 = p[256];        // (i=0,j=1)
        float v10 = p[64 * 256];   // (i=1,j=0)
        float v11 = p[65 * 256];   // (i=1,j=1)

        float* ob = out + ((size_t)b * 48 + t * 16) * 256 + c;
#pragma unroll
        for (int gh = 0; gh < 4; ++gh) {
            float u0 = wa[gh] * v00 + wb[gh] * v10;  // interp along i (rows)
            float u1 = wa[gh] * v01 + wb[gh] * v11;
#pragma unroll
            for (int gw = 0; gw < 4; ++gw) {
                float val = wa[gw] * u0 + wb[gw] * u1;  // interp along j (cols)
                ob[(gh * 4 + gw) * 256] = val * s_gmap[gh * 4 + gw];
            }
        }
    }
}

// ---------------------------------------------------------------------------
extern "C" void kernel_launch(void* const* d_in, const int* in_sizes, int n_in,
                              void* d_out, int out_size) {
    const float* z   = (const float*)d_in[0];
    const float* x   = (const float*)d_in[1];
    const float* gth = (const float*)d_in[2];
    const float* gsg = (const float*)d_in[3];
    const float* glm = (const float*)d_in[4];
    const float* gps = (const float*)d_in[5];
    const float* ggm = (const float*)d_in[6];
    const float* gwt = (const float*)d_in[7];
    float* out = (float*)d_out;

    int B = in_sizes[0] / (64 * 256);   // z is (B, 64, 256)

    k_zmax  <<<B,      256>>>(z, gth, gsg, glm, gps, ggm, gwt);
    k_winsum<<<B * 32, 256>>>(x);
    k_tail  <<<B,      256>>>(x, out);
}

// round 3
// speedup vs baseline: 1.1770x; 1.1468x over previous
#include <cuda_runtime.h>
#include <math_constants.h>
#include <float.h>

// Problem constants (fixed by setup_inputs): B=64, Nt=64, Ns=4096, C=256,
// WIN=2, TOPK=3, GH=GW=4, 16 gabor kernels.
#define BMAX 64

__device__ float g_zmax[BMAX * 256];
__device__ float g_winsum[BMAX * 1024];
__device__ float g_gmap[16];

// ---------------------------------------------------------------------------
// Kernel 1: z_max[b,c] = max over 64 tokens of z[b,t,c].
// 1024 threads/block: 4 token-chunks x 256 channels, smem reduce -> high MLP.
// Block 0 threads 0..255 additionally compute the 4x4 gabor map fully in
// parallel: one thread per (cell, k) term, width-16 shuffle reduction.
// ---------------------------------------------------------------------------
__global__ void __launch_bounds__(1024) k_zmax(
        const float* __restrict__ z,
        const float* __restrict__ gth, const float* __restrict__ gsg,
        const float* __restrict__ glm, const float* __restrict__ gps,
        const float* __restrict__ ggm, const float* __restrict__ gwt) {
    int b = blockIdx.x;
    int tid = threadIdx.x;
    int g = tid >> 8;          // token chunk 0..3
    int c = tid & 255;         // channel
    __shared__ float sm[4][256];

    const float* p = z + ((size_t)b * 64 + g * 16) * 256 + c;
    float m = -FLT_MAX;
#pragma unroll
    for (int t = 0; t < 16; ++t) m = fmaxf(m, p[t * 256]);
    sm[g][c] = m;

    // Gabor map: 16 cells x 16 kernels, one term per thread (block 0 only).
    if (b == 0 && tid < 256) {
        int cell = tid >> 4;       // 0..15 -> (h,w)
        int k    = tid & 15;       // gabor kernel index
        int h = cell >> 2, w = cell & 3;
        float yy = (float)h - 1.5f;
        float xx = (float)w - 1.5f;
        float theta = gth[k] * (2.f * CUDART_PI_F);
        float ct = cosf(theta), st = sinf(theta);
        float xp =  xx * ct + yy * st;
        float yp = -xx * st + yy * ct;
        float sig = gsg[k] + 0.5f;
        float lmb = glm[k] + 0.5f;
        float gam = ggm[k];
        float env = expf(-(xp * xp + gam * gam * yp * yp) / (2.f * sig * sig));
        float car = cosf(2.f * CUDART_PI_F * xp / lmb + gps[k]);
        float term = gwt[k] * env * car;
#pragma unroll
        for (int o = 8; o > 0; o >>= 1)
            term += __shfl_down_sync(0xffffffffu, term, o, 16);
        if (k == 0) g_gmap[cell] = 1.f + term;   // splat + x_up = x_up*(1+gmap)
    }

    __syncthreads();
    if (g == 0) {
        float r = fmaxf(fmaxf(sm[0][c], sm[1][c]), fmaxf(sm[2][c], sm[3][c]));
        g_zmax[b * 256 + c] = r;
    }
}

// ---------------------------------------------------------------------------
// Kernel 2: per-window sum of response over the 4 pixels of each 2x2 window.
// winsum[b, wh*32+ww] = sum_{i,j} dot(x[b, (2wh+i)*64 + 2ww+j, :], zmax[b,:])
// One block per (b, wh). 8 warps; each warp owns 4 windows with independent
// accumulators; loads front-batched per row-pair for MLP; shuffles at end.
// ---------------------------------------------------------------------------
__global__ void __launch_bounds__(256) k_winsum(const float* __restrict__ x) {
    int b  = blockIdx.x >> 5;
    int wh = blockIdx.x & 31;
    __shared__ float4 sz[64];
    int tid = threadIdx.x;
    if (tid < 64) sz[tid] = ((const float4*)(g_zmax + b * 256))[tid];
    __syncthreads();

    int warp = tid >> 5, lane = tid & 31;
    const float* xb = x + (size_t)b * 4096 * 256 + (size_t)wh * 128 * 256
                        + (size_t)warp * 4 * 2 * 256;

    float acc[4] = {0.f, 0.f, 0.f, 0.f};
#pragma unroll
    for (int r = 0; r < 4; ++r) {
        int off = ((r >> 1) * 64 + (r & 1)) * 256;   // rows s, s+1, s+64, s+65
        float4 va[4], vb[4];
#pragma unroll
        for (int q = 0; q < 4; ++q) {                // batch 8 loads before FMAs
            const float4* p4 = (const float4*)(xb + q * 512 + off);
            va[q] = p4[lane];
            vb[q] = p4[lane + 32];
        }
        float4 za = sz[lane], zb = sz[lane + 32];
#pragma unroll
        for (int q = 0; q < 4; ++q) {
            acc[q] += va[q].x * za.x + va[q].y * za.y + va[q].z * za.z + va[q].w * za.w;
            acc[q] += vb[q].x * zb.x + vb[q].y * zb.y + vb[q].z * zb.z + vb[q].w * zb.w;
        }
    }
#pragma unroll
    for (int q = 0; q < 4; ++q) {
        float a = acc[q];
#pragma unroll
        for (int o = 16; o > 0; o >>= 1) a += __shfl_down_sync(0xffffffffu, a, o);
        if (lane == 0) g_winsum[b * 1024 + wh * 32 + warp * 4 + q] = a;
    }
}

// ---------------------------------------------------------------------------
// Kernel 3 (fused tail): per-batch top-3 window select (descending, ties ->
// lowest index, matching jax.lax.top_k), then gather + bilinear 2->4 upsample
// + (1+gmap) scale + write. One block per batch, thread per channel.
// jax half-pixel bilinear 2->4 weights: {1,0},{.75,.25},{.25,.75},{0,1}.
// ---------------------------------------------------------------------------
__global__ void __launch_bounds__(256) k_tail(const float* __restrict__ x,
                                              float* __restrict__ out) {
    int b = blockIdx.x;
    __shared__ float sv[1024];
    __shared__ float rv[256];
    __shared__ int   ri[256];
    __shared__ int   sidx[3];
    __shared__ float s_gmap[16];
    int tid = threadIdx.x;
#pragma unroll
    for (int k = 0; k < 4; ++k) sv[tid + k * 256] = g_winsum[b * 1024 + tid + k * 256];
    if (tid < 16) s_gmap[tid] = g_gmap[tid];
    __syncthreads();

    for (int r = 0; r < 3; ++r) {
        float bv = -FLT_MAX; int bi = 1 << 30;
#pragma unroll
        for (int k = 0; k < 4; ++k) {
            int i = tid + k * 256;
            float v = sv[i];
            if (v > bv || (v == bv && i < bi)) { bv = v; bi = i; }
        }
        rv[tid] = bv; ri[tid] = bi;
        __syncthreads();
        for (int s = 128; s > 0; s >>= 1) {
            if (tid < s) {
                float ov = rv[tid + s]; int oi = ri[tid + s];
                if (ov > rv[tid] || (ov == rv[tid] && oi < ri[tid])) { rv[tid] = ov; ri[tid] = oi; }
            }
            __syncthreads();
        }
        if (tid == 0) { sidx[r] = ri[0]; sv[ri[0]] = -FLT_MAX; }
        __syncthreads();
    }

    const float wa[4] = {1.f, 0.75f, 0.25f, 0.f};
    const float wb[4] = {0.f, 0.25f, 0.75f, 1.f};
    int c = tid;

#pragma unroll
    for (int t = 0; t < 3; ++t) {
        int widx = sidx[t];
        int wh = widx >> 5, ww = widx & 31;
        const float* p = x + ((size_t)b * 4096 + wh * 128 + ww * 2) * 256 + c;
        float v00 = p[0];          // (i=0,j=0)
        float v01 = p[256];        // (i=0,j=1)
        float v10 = p[64 * 256];   // (i=1,j=0)
        float v11 = p[65 * 256];   // (i=1,j=1)

        float* ob = out + ((size_t)b * 48 + t * 16) * 256 + c;
#pragma unroll
        for (int gh = 0; gh < 4; ++gh) {
            float u0 = wa[gh] * v00 + wb[gh] * v10;  // interp along i (rows)
            float u1 = wa[gh] * v01 + wb[gh] * v11;
#pragma unroll
            for (int gw = 0; gw < 4; ++gw) {
                float val = wa[gw] * u0 + wb[gw] * u1;  // interp along j (cols)
                ob[(gh * 4 + gw) * 256] = val * s_gmap[gh * 4 + gw];
            }
        }
    }
}

// ---------------------------------------------------------------------------
extern "C" void kernel_launch(void* const* d_in, const int* in_sizes, int n_in,
                              void* d_out, int out_size) {
    const float* z   = (const float*)d_in[0];
    const float* x   = (const float*)d_in[1];
    const float* gth = (const float*)d_in[2];
    const float* gsg = (const float*)d_in[3];
    const float* glm = (const float*)d_in[4];
    const float* gps = (const float*)d_in[5];
    const float* ggm = (const float*)d_in[6];
    const float* gwt = (const float*)d_in[7];
    float* out = (float*)d_out;

    int B = in_sizes[0] / (64 * 256);   // z is (B, 64, 256)

    k_zmax  <<<B,      1024>>>(z, gth, gsg, glm, gps, ggm, gwt);
    k_winsum<<<B * 32, 256>>>(x);
    k_tail  <<<B,      256>>>(x, out);
}